// round 6
// baseline (speedup 1.0000x reference)
#include <cuda_runtime.h>
#include <math.h>

#define N_TOK   4096
#define DMODEL  256
#define NHEAD   4
#define DPH     64
#define NEXP    9
#define LN_EPS  1e-5f
#define ATT_SCALE 0.25f   // (dph // num_heads) ** -0.5 = 16^-0.5

typedef unsigned long long ull;

// -------- device scratch (sorted-domain layout) --------
__device__ float g_q[N_TOK * DMODEL];
__device__ float g_k[N_TOK * DMODEL];
__device__ float g_v[N_TOK * DMODEL];
__device__ float g_ctx[N_TOK * DMODEL];
__device__ float g_h[N_TOK * DMODEL];
__device__ int   g_perm[N_TOK];       // sorted pos -> original token
__device__ int   g_offsets[NEXP + 1];

// -------- f32x2 packed math helpers (sm_100+) --------
__device__ __forceinline__ ull fma2(ull a, ull b, ull c) {
    ull d;
    asm("fma.rn.f32x2 %0, %1, %2, %3;" : "=l"(d) : "l"(a), "l"(b), "l"(c));
    return d;
}
__device__ __forceinline__ ull pack2(float x) {
    ull d; asm("mov.b64 %0, {%1, %1};" : "=l"(d) : "f"(x)); return d;
}
__device__ __forceinline__ float2 unpack2(ull v) {
    float2 r; asm("mov.b64 {%0, %1}, %2;" : "=f"(r.x), "=f"(r.y) : "l"(v)); return r;
}

// -------- fused counting sort (1 block) --------
__global__ void k_sort(const int* __restrict__ label) {
    __shared__ int hist[NEXP], base[NEXP + 1], cur[NEXP];
    int t = threadIdx.x;
    if (t < NEXP) { hist[t] = 0; cur[t] = 0; }
    __syncthreads();
    for (int i = t; i < N_TOK; i += 1024) atomicAdd(&hist[label[i]], 1);
    __syncthreads();
    if (t == 0) {
        int off = 0;
        for (int e = 0; e < NEXP; e++) { base[e] = off; g_offsets[e] = off; off += hist[e]; }
        base[NEXP] = off; g_offsets[NEXP] = off;
    }
    __syncthreads();
    for (int i = t; i < N_TOK; i += 1024) {
        int l = label[i];
        int p = atomicAdd(&cur[l], 1);
        g_perm[base[l] + p] = i;
    }
}

// -------- grouped QKV GEMM: 64x128 tile, 4x8/thread, f32x2, prefetched --------
// grid (64, 2, 27), block 256. Output rows stored in SORTED order.
__global__ __launch_bounds__(256) void k_qkv(
    const float* __restrict__ x,
    const float* __restrict__ Wq, const float* __restrict__ bq,
    const float* __restrict__ Wk, const float* __restrict__ bk,
    const float* __restrict__ Wv, const float* __restrict__ bv)
{
    int g   = blockIdx.z % NEXP;
    int mat = blockIdx.z / NEXP;
    int goff = g_offsets[g];
    int gcnt = g_offsets[g + 1] - goff;
    int row0 = blockIdx.x * 64;
    if (row0 >= gcnt) return;
    int rows = min(64, gcnt - row0);
    int col0 = blockIdx.y * 128;

    const float* W; const float* bias; float* dst;
    if (mat == 0)      { W = Wq; bias = bq; dst = g_q; }
    else if (mat == 1) { W = Wk; bias = bk; dst = g_k; }
    else               { W = Wv; bias = bv; dst = g_v; }
    W    += (size_t)g * DMODEL * DMODEL;
    bias += g * DMODEL;

    __shared__ __align__(16) float As[16 * 64];    // [k][m] transposed
    __shared__ __align__(16) float Bs[16 * 128];   // [k][n]
    __shared__ int Ts[64];

    int tid = threadIdx.x;
    if (tid < 64) Ts[tid] = g_perm[goff + row0 + min(tid, rows - 1)];
    __syncthreads();

    int r = tid >> 4, c = tid & 15;     // rows 4r..4r+3, cols 4c & 64+4c
    ull acc[4][4];
#pragma unroll
    for (int i = 0; i < 4; i++)
#pragma unroll
        for (int j = 0; j < 4; j++) acc[i][j] = 0ull;

    int am = tid & 63, aseg = tid >> 6;           // A loader: row am, k-dims 4aseg..
    int bkk = tid >> 4, bn = (tid & 15) * 8;      // B loader
    const float* Aptr = x + (size_t)Ts[am] * DMODEL + aseg * 4;
    const float* Bptr = W + (size_t)bkk * DMODEL + col0 + bn;

    float4 av  = *(const float4*)(Aptr);
    float4 bv0 = *(const float4*)(Bptr);
    float4 bv1 = *(const float4*)(Bptr + 4);

    for (int kk0 = 0; kk0 < DMODEL; kk0 += 16) {
        __syncthreads();   // previous compute done reading smem
        As[(aseg * 4 + 0) * 64 + am] = av.x;
        As[(aseg * 4 + 1) * 64 + am] = av.y;
        As[(aseg * 4 + 2) * 64 + am] = av.z;
        As[(aseg * 4 + 3) * 64 + am] = av.w;
        *(float4*)&Bs[bkk * 128 + bn]     = bv0;
        *(float4*)&Bs[bkk * 128 + bn + 4] = bv1;
        __syncthreads();
        if (kk0 + 16 < DMODEL) {       // prefetch next k-slab; hides under compute
            av  = *(const float4*)(Aptr + kk0 + 16);
            bv0 = *(const float4*)(Bptr + (size_t)(kk0 + 16) * DMODEL);
            bv1 = *(const float4*)(Bptr + (size_t)(kk0 + 16) * DMODEL + 4);
        }
#pragma unroll
        for (int k = 0; k < 16; k++) {
            float4 a = *(const float4*)&As[k * 64 + 4 * r];
            ulonglong2 B0 = *(const ulonglong2*)&Bs[k * 128 + 4 * c];
            ulonglong2 B1 = *(const ulonglong2*)&Bs[k * 128 + 64 + 4 * c];
            ull a0 = pack2(a.x), a1 = pack2(a.y), a2 = pack2(a.z), a3 = pack2(a.w);
            acc[0][0] = fma2(a0, B0.x, acc[0][0]); acc[0][1] = fma2(a0, B0.y, acc[0][1]);
            acc[0][2] = fma2(a0, B1.x, acc[0][2]); acc[0][3] = fma2(a0, B1.y, acc[0][3]);
            acc[1][0] = fma2(a1, B0.x, acc[1][0]); acc[1][1] = fma2(a1, B0.y, acc[1][1]);
            acc[1][2] = fma2(a1, B1.x, acc[1][2]); acc[1][3] = fma2(a1, B1.y, acc[1][3]);
            acc[2][0] = fma2(a2, B0.x, acc[2][0]); acc[2][1] = fma2(a2, B0.y, acc[2][1]);
            acc[2][2] = fma2(a2, B1.x, acc[2][2]); acc[2][3] = fma2(a2, B1.y, acc[2][3]);
            acc[3][0] = fma2(a3, B0.x, acc[3][0]); acc[3][1] = fma2(a3, B0.y, acc[3][1]);
            acc[3][2] = fma2(a3, B1.x, acc[3][2]); acc[3][3] = fma2(a3, B1.y, acc[3][3]);
        }
    }

    float4 bias0 = *(const float4*)&bias[col0 + 4 * c];
    float4 bias1 = *(const float4*)&bias[col0 + 64 + 4 * c];
#pragma unroll
    for (int i = 0; i < 4; i++) {
        int m = 4 * r + i;
        if (m < rows) {
            float* drow = dst + (size_t)(goff + row0 + m) * DMODEL;
            float2 p0 = unpack2(acc[i][0]), p1 = unpack2(acc[i][1]);
            float4 o0 = {p0.x + bias0.x, p0.y + bias0.y, p1.x + bias0.z, p1.y + bias0.w};
            *(float4*)&drow[col0 + 4 * c] = o0;
            float2 p2 = unpack2(acc[i][2]), p3 = unpack2(acc[i][3]);
            float4 o1 = {p2.x + bias1.x, p2.y + bias1.y, p3.x + bias1.z, p3.y + bias1.w};
            *(float4*)&drow[col0 + 64 + 4 * c] = o1;
        }
    }
}

// -------- per-group flash attention: no-max softmax (scores bounded), deferred l-reduce --------
// grid (64, 9, 4), block 256, dynamic smem 69632B.
__global__ __launch_bounds__(256) void k_attn()
{
    int g = blockIdx.y, h = blockIdx.z;
    int goff = g_offsets[g];
    int gcnt = g_offsets[g + 1] - goff;
    int row0 = blockIdx.x * 64;
    if (row0 >= gcnt) return;
    int rows = min(64, gcnt - row0);

    extern __shared__ __align__(16) float sm[];
    float* Qt = sm;                  // [d][qi] pitch 68 (pre-scaled by ATT_SCALE)
    float* Kt = Qt + 64 * 68;        // [d][kj] pitch 68
    float* Vs = Kt + 64 * 68;        // [kj][d] pitch 68
    float* Ps = Vs + 64 * 68;        // [qi][kj] pitch 68

    int tid = threadIdx.x;
    int r = tid >> 4, c = tid & 15;
    int li = tid & 63, seg = tid >> 6, d0 = seg * 16;  // loader mapping

    // load Q transposed, pre-scaled (once)
    {
        const float* qptr = g_q + (size_t)(goff + row0 + min(li, rows - 1)) * DMODEL + h * DPH + d0;
#pragma unroll
        for (int f = 0; f < 4; f++) {
            float4 v = *(const float4*)(qptr + 4 * f);
            Qt[(d0 + 4 * f + 0) * 68 + li] = v.x * ATT_SCALE;
            Qt[(d0 + 4 * f + 1) * 68 + li] = v.y * ATT_SCALE;
            Qt[(d0 + 4 * f + 2) * 68 + li] = v.z * ATT_SCALE;
            Qt[(d0 + 4 * f + 3) * 68 + li] = v.w * ATT_SCALE;
        }
    }

    float lsum[4] = {0.f, 0.f, 0.f, 0.f};   // per-lane partial row sums
    ull O2[4][2];
#pragma unroll
    for (int i = 0; i < 4; i++) { O2[i][0] = 0ull; O2[i][1] = 0ull; }

    // prefetch tile 0 K/V into registers
    float4 kr[4], vr[4];
    {
        int kcnt0 = min(64, gcnt);
        int krow = goff + min(li, kcnt0 - 1);
        const float* kptr = g_k + (size_t)krow * DMODEL + h * DPH + d0;
        const float* vptr = g_v + (size_t)krow * DMODEL + h * DPH + d0;
#pragma unroll
        for (int f = 0; f < 4; f++) {
            kr[f] = *(const float4*)(kptr + 4 * f);
            vr[f] = *(const float4*)(vptr + 4 * f);
        }
    }

    for (int kc0 = 0; kc0 < gcnt; kc0 += 64) {
        int kcnt = min(64, gcnt - kc0);
        __syncthreads();   // prior PV reads done (first iter: Q stores ordered)
#pragma unroll
        for (int f = 0; f < 4; f++) {
            Kt[(d0 + 4 * f + 0) * 68 + li] = kr[f].x;
            Kt[(d0 + 4 * f + 1) * 68 + li] = kr[f].y;
            Kt[(d0 + 4 * f + 2) * 68 + li] = kr[f].z;
            Kt[(d0 + 4 * f + 3) * 68 + li] = kr[f].w;
            *(float4*)&Vs[li * 68 + d0 + 4 * f] = vr[f];
        }
        __syncthreads();

        // ---- QK^T (f32x2) ----
        ull s2[4][2];
#pragma unroll
        for (int i = 0; i < 4; i++) { s2[i][0] = 0ull; s2[i][1] = 0ull; }
#pragma unroll 8
        for (int d = 0; d < 64; d++) {
            float4 a = *(const float4*)&Qt[d * 68 + 4 * r];
            ulonglong2 b = *(const ulonglong2*)&Kt[d * 68 + 4 * c];
            ull a0 = pack2(a.x), a1 = pack2(a.y), a2 = pack2(a.z), a3 = pack2(a.w);
            s2[0][0] = fma2(a0, b.x, s2[0][0]); s2[0][1] = fma2(a0, b.y, s2[0][1]);
            s2[1][0] = fma2(a1, b.x, s2[1][0]); s2[1][1] = fma2(a1, b.y, s2[1][1]);
            s2[2][0] = fma2(a2, b.x, s2[2][0]); s2[2][1] = fma2(a2, b.y, s2[2][1]);
            s2[3][0] = fma2(a3, b.x, s2[3][0]); s2[3][1] = fma2(a3, b.y, s2[3][1]);
        }

        // ---- exp (fixed m=0; scores bounded) + per-lane partial sum ----
        bool va0 = (4 * c + 0) < kcnt, va1 = (4 * c + 1) < kcnt;
        bool va2 = (4 * c + 2) < kcnt, va3 = (4 * c + 3) < kcnt;
#pragma unroll
        for (int i = 0; i < 4; i++) {
            float2 sa = unpack2(s2[i][0]);
            float2 sb = unpack2(s2[i][1]);
            float p0 = va0 ? __expf(sa.x) : 0.f;
            float p1 = va1 ? __expf(sa.y) : 0.f;
            float p2 = va2 ? __expf(sb.x) : 0.f;
            float p3 = va3 ? __expf(sb.y) : 0.f;
            lsum[i] += (p0 + p1) + (p2 + p3);
            float4 pv = {p0, p1, p2, p3};
            *(float4*)&Ps[(4 * r + i) * 68 + 4 * c] = pv;
        }

        // prefetch next tile K/V (latency hides under PV below)
        if (kc0 + 64 < gcnt) {
            int kcn = min(64, gcnt - kc0 - 64);
            int krow = goff + kc0 + 64 + min(li, kcn - 1);
            const float* kptr = g_k + (size_t)krow * DMODEL + h * DPH + d0;
            const float* vptr = g_v + (size_t)krow * DMODEL + h * DPH + d0;
#pragma unroll
            for (int f = 0; f < 4; f++) {
                kr[f] = *(const float4*)(kptr + 4 * f);
                vr[f] = *(const float4*)(vptr + 4 * f);
            }
        }
        __syncthreads();

        // ---- P @ V (f32x2, vectorized over 4 keys) ----
#pragma unroll 4
        for (int kj = 0; kj < 64; kj += 4) {
            float4 pp0 = *(const float4*)&Ps[(4 * r + 0) * 68 + kj];
            float4 pp1 = *(const float4*)&Ps[(4 * r + 1) * 68 + kj];
            float4 pp2 = *(const float4*)&Ps[(4 * r + 2) * 68 + kj];
            float4 pp3 = *(const float4*)&Ps[(4 * r + 3) * 68 + kj];
#pragma unroll
            for (int j = 0; j < 4; j++) {
                ulonglong2 vv = *(const ulonglong2*)&Vs[(kj + j) * 68 + 4 * c];
                float p0 = (j == 0) ? pp0.x : (j == 1) ? pp0.y : (j == 2) ? pp0.z : pp0.w;
                float p1 = (j == 0) ? pp1.x : (j == 1) ? pp1.y : (j == 2) ? pp1.z : pp1.w;
                float p2 = (j == 0) ? pp2.x : (j == 1) ? pp2.y : (j == 2) ? pp2.z : pp2.w;
                float p3 = (j == 0) ? pp3.x : (j == 1) ? pp3.y : (j == 2) ? pp3.z : pp3.w;
                ull q0 = pack2(p0), q1 = pack2(p1), q2 = pack2(p2), q3 = pack2(p3);
                O2[0][0] = fma2(q0, vv.x, O2[0][0]); O2[0][1] = fma2(q0, vv.y, O2[0][1]);
                O2[1][0] = fma2(q1, vv.x, O2[1][0]); O2[1][1] = fma2(q1, vv.y, O2[1][1]);
                O2[2][0] = fma2(q2, vv.x, O2[2][0]); O2[2][1] = fma2(q2, vv.y, O2[2][1]);
                O2[3][0] = fma2(q3, vv.x, O2[3][0]); O2[3][1] = fma2(q3, vv.y, O2[3][1]);
            }
        }
    }

    // single deferred row-sum reduction across the 16 c-lanes
#pragma unroll
    for (int i = 0; i < 4; i++) {
        float ps = lsum[i];
        ps += __shfl_xor_sync(0xffffffffu, ps, 1);
        ps += __shfl_xor_sync(0xffffffffu, ps, 2);
        ps += __shfl_xor_sync(0xffffffffu, ps, 4);
        ps += __shfl_xor_sync(0xffffffffu, ps, 8);
        lsum[i] = ps;
    }

#pragma unroll
    for (int i = 0; i < 4; i++) {
        int qrow = 4 * r + i;
        if (qrow < rows) {
            float inv = 1.f / lsum[i];
            float2 oa = unpack2(O2[i][0]);
            float2 ob = unpack2(O2[i][1]);
            float4 o = {oa.x * inv, oa.y * inv, ob.x * inv, ob.y * inv};
            *(float4*)&g_ctx[(size_t)(goff + row0 + qrow) * DMODEL + h * DPH + 4 * c] = o;
        }
    }
}

// -------- output projection + residual: 64x128 tile, 4x8/thread, f32x2, prefetched --------
// grid (64, 2), block 256. g_h[sorted] = x[perm] + ctx[sorted] @ Wf + bf
__global__ __launch_bounds__(256) void k_proj(
    const float* __restrict__ x,
    const float* __restrict__ Wf, const float* __restrict__ bf)
{
    int row0 = blockIdx.x * 64;
    int col0 = blockIdx.y * 128;

    __shared__ __align__(16) float As[16 * 64];    // [k][m] transposed
    __shared__ __align__(16) float Bs[16 * 128];   // [k][n]
    __shared__ int Ts[64];

    int tid = threadIdx.x;
    if (tid < 64) Ts[tid] = g_perm[row0 + tid];

    int r = tid >> 4, c = tid & 15;     // rows 4r..4r+3, cols 4c & 64+4c
    ull acc[4][4];
#pragma unroll
    for (int i = 0; i < 4; i++)
#pragma unroll
        for (int j = 0; j < 4; j++) acc[i][j] = 0ull;

    int am = tid & 63, aseg = tid >> 6;           // A loader: row am, k-dims 4aseg..
    int bkk = tid >> 4, bn = (tid & 15) * 8;      // B loader: k-row bkk, cols bn..bn+8
    const float* Aptr = g_ctx + (size_t)(row0 + am) * DMODEL + aseg * 4;
    const float* Bptr = Wf + (size_t)bkk * DMODEL + col0 + bn;

    float4 av = *(const float4*)(Aptr);
    float4 bv0 = *(const float4*)(Bptr);
    float4 bv1 = *(const float4*)(Bptr + 4);

    for (int kk0 = 0; kk0 < DMODEL; kk0 += 16) {
        __syncthreads();
        As[(aseg * 4 + 0) * 64 + am] = av.x;
        As[(aseg * 4 + 1) * 64 + am] = av.y;
        As[(aseg * 4 + 2) * 64 + am] = av.z;
        As[(aseg * 4 + 3) * 64 + am] = av.w;
        *(float4*)&Bs[bkk * 128 + bn]     = bv0;
        *(float4*)&Bs[bkk * 128 + bn + 4] = bv1;
        __syncthreads();
        if (kk0 + 16 < DMODEL) {
            av  = *(const float4*)(Aptr + kk0 + 16);
            bv0 = *(const float4*)(Bptr + (size_t)(kk0 + 16) * DMODEL);
            bv1 = *(const float4*)(Bptr + (size_t)(kk0 + 16) * DMODEL + 4);
        }
#pragma unroll
        for (int k = 0; k < 16; k++) {
            float4 a = *(const float4*)&As[k * 64 + 4 * r];
            ulonglong2 B0 = *(const ulonglong2*)&Bs[k * 128 + 4 * c];
            ulonglong2 B1 = *(const ulonglong2*)&Bs[k * 128 + 64 + 4 * c];
            ull a0 = pack2(a.x), a1 = pack2(a.y), a2 = pack2(a.z), a3 = pack2(a.w);
            acc[0][0] = fma2(a0, B0.x, acc[0][0]); acc[0][1] = fma2(a0, B0.y, acc[0][1]);
            acc[0][2] = fma2(a0, B1.x, acc[0][2]); acc[0][3] = fma2(a0, B1.y, acc[0][3]);
            acc[1][0] = fma2(a1, B0.x, acc[1][0]); acc[1][1] = fma2(a1, B0.y, acc[1][1]);
            acc[1][2] = fma2(a1, B1.x, acc[1][2]); acc[1][3] = fma2(a1, B1.y, acc[1][3]);
            acc[2][0] = fma2(a2, B0.x, acc[2][0]); acc[2][1] = fma2(a2, B0.y, acc[2][1]);
            acc[2][2] = fma2(a2, B1.x, acc[2][2]); acc[2][3] = fma2(a2, B1.y, acc[2][3]);
            acc[3][0] = fma2(a3, B0.x, acc[3][0]); acc[3][1] = fma2(a3, B0.y, acc[3][1]);
            acc[3][2] = fma2(a3, B1.x, acc[3][2]); acc[3][3] = fma2(a3, B1.y, acc[3][3]);
        }
    }

    float4 bias0 = *(const float4*)&bf[col0 + 4 * c];
    float4 bias1 = *(const float4*)&bf[col0 + 64 + 4 * c];
#pragma unroll
    for (int i = 0; i < 4; i++) {
        int m = 4 * r + i;
        const float* xr = x + (size_t)Ts[m] * DMODEL;
        float* hrow = g_h + (size_t)(row0 + m) * DMODEL;
        float4 xv0 = *(const float4*)&xr[col0 + 4 * c];
        float2 p0 = unpack2(acc[i][0]), p1 = unpack2(acc[i][1]);
        float4 o0 = {p0.x + bias0.x + xv0.x, p0.y + bias0.y + xv0.y,
                     p1.x + bias0.z + xv0.z, p1.y + bias0.w + xv0.w};
        *(float4*)&hrow[col0 + 4 * c] = o0;
        float4 xv1 = *(const float4*)&xr[col0 + 64 + 4 * c];
        float2 p2 = unpack2(acc[i][2]), p3 = unpack2(acc[i][3]);
        float4 o1 = {p2.x + bias1.x + xv1.x, p2.y + bias1.y + xv1.y,
                     p3.x + bias1.z + xv1.z, p3.y + bias1.w + xv1.w};
        *(float4*)&hrow[col0 + 64 + 4 * c] = o1;
    }
}

// -------- LayerNorm (sorted row -> scatter to original) --------
__global__ void k_ln(const float* __restrict__ gamma, const float* __restrict__ beta,
                     float* __restrict__ out)
{
    int srow = blockIdx.x;
    int tid = threadIdx.x;
    float v = g_h[(size_t)srow * DMODEL + tid];
    float s = v, sq = v * v;
#pragma unroll
    for (int off = 16; off > 0; off >>= 1) {
        s  += __shfl_xor_sync(0xffffffffu, s, off);
        sq += __shfl_xor_sync(0xffffffffu, sq, off);
    }
    __shared__ float rs[8], rq[8];
    int w = tid >> 5;
    if ((tid & 31) == 0) { rs[w] = s; rq[w] = sq; }
    __syncthreads();
    s = 0.f; sq = 0.f;
#pragma unroll
    for (int i = 0; i < 8; i++) { s += rs[i]; sq += rq[i]; }
    float mean = s * (1.f / DMODEL);
    float var  = sq * (1.f / DMODEL) - mean * mean;
    float inv  = rsqrtf(var + LN_EPS);
    int orow = g_perm[srow];
    out[(size_t)orow * DMODEL + tid] = gamma[tid] * (v - mean) * inv + beta[tid];
}

// -------- launch --------
extern "C" void kernel_launch(void* const* d_in, const int* in_sizes, int n_in,
                              void* d_out, int out_size)
{
    const float* x     = (const float*)d_in[0];
    const int*   label = (const int*)  d_in[1];
    const float* Wq    = (const float*)d_in[2];
    const float* bq    = (const float*)d_in[3];
    const float* Wk    = (const float*)d_in[4];
    const float* bk    = (const float*)d_in[5];
    const float* Wv    = (const float*)d_in[6];
    const float* bv    = (const float*)d_in[7];
    const float* Wf    = (const float*)d_in[8];
    const float* bf    = (const float*)d_in[9];
    const float* gamma = (const float*)d_in[10];
    const float* beta  = (const float*)d_in[11];
    float* out = (float*)d_out;

    static bool attr_done = false;
    if (!attr_done) {
        cudaFuncSetAttribute(k_attn, cudaFuncAttributeMaxDynamicSharedMemorySize, 4 * 64 * 68 * 4);
        // Maximize the smem carveout so two 69.6KB attn blocks can co-reside per SM.
        cudaFuncSetAttribute(k_attn, cudaFuncAttributePreferredSharedMemoryCarveout, 100);
        cudaFuncSetAttribute(k_qkv,  cudaFuncAttributePreferredSharedMemoryCarveout, 100);
        cudaFuncSetAttribute(k_proj, cudaFuncAttributePreferredSharedMemoryCarveout, 100);
        attr_done = true;
    }

    k_sort<<<1, 1024>>>(label);
    k_qkv<<<dim3(64, 2, 3 * NEXP), 256>>>(x, Wq, bq, Wk, bk, Wv, bv);
    k_attn<<<dim3(64, NEXP, NHEAD), 256, 4 * 64 * 68 * 4>>>();
    k_proj<<<dim3(64, 2), 256>>>(x, Wf, bf);
    k_ln<<<N_TOK, 256>>>(gamma, beta, out);
}

// round 7
// speedup vs baseline: 1.1591x; 1.1591x over previous
#include <cuda_runtime.h>
#include <math.h>

#define N_TOK   4096
#define DMODEL  256
#define NHEAD   4
#define DPH     64
#define NEXP    9
#define LN_EPS  1e-5f
#define ATT_SCALE 0.25f   // (dph // num_heads) ** -0.5 = 16^-0.5

typedef unsigned long long ull;
typedef unsigned int uint;

// -------- device scratch (sorted-domain layout) --------
__device__ float g_q[N_TOK * DMODEL];
__device__ float g_k[N_TOK * DMODEL];
__device__ float g_v[N_TOK * DMODEL];
__device__ float g_ctx[N_TOK * DMODEL];
__device__ float g_h[N_TOK * DMODEL];
__device__ int   g_perm[N_TOK];       // sorted pos -> original token
__device__ int   g_offsets[NEXP + 1];

// -------- f32x2 packed math helpers (sm_100+) --------
__device__ __forceinline__ ull fma2(ull a, ull b, ull c) {
    ull d;
    asm("fma.rn.f32x2 %0, %1, %2, %3;" : "=l"(d) : "l"(a), "l"(b), "l"(c));
    return d;
}
__device__ __forceinline__ ull pack2(float x) {
    ull d; asm("mov.b64 %0, {%1, %1};" : "=l"(d) : "f"(x)); return d;
}
__device__ __forceinline__ float2 unpack2(ull v) {
    float2 r; asm("mov.b64 {%0, %1}, %2;" : "=f"(r.x), "=f"(r.y) : "l"(v)); return r;
}

// -------- tf32 mma helpers --------
__device__ __forceinline__ uint cvt_tf32(float x) {
    uint u; asm("cvt.rna.tf32.f32 %0, %1;" : "=r"(u) : "f"(x)); return u;
}
__device__ __forceinline__ void mma_tf32(float* d, const uint* a, uint b0, uint b1) {
    asm("mma.sync.aligned.m16n8k8.row.col.f32.tf32.tf32.f32 "
        "{%0,%1,%2,%3}, {%4,%5,%6,%7}, {%8,%9}, {%0,%1,%2,%3};"
        : "+f"(d[0]), "+f"(d[1]), "+f"(d[2]), "+f"(d[3])
        : "r"(a[0]), "r"(a[1]), "r"(a[2]), "r"(a[3]), "r"(b0), "r"(b1));
}

#define AP 20    // As pitch (uints)
#define BP 132   // Bs pitch (uints)

// -------- fused counting sort (1 block) --------
__global__ void k_sort(const int* __restrict__ label) {
    __shared__ int hist[NEXP], base[NEXP + 1], cur[NEXP];
    int t = threadIdx.x;
    if (t < NEXP) { hist[t] = 0; cur[t] = 0; }
    __syncthreads();
    for (int i = t; i < N_TOK; i += 1024) atomicAdd(&hist[label[i]], 1);
    __syncthreads();
    if (t == 0) {
        int off = 0;
        for (int e = 0; e < NEXP; e++) { base[e] = off; g_offsets[e] = off; off += hist[e]; }
        base[NEXP] = off; g_offsets[NEXP] = off;
    }
    __syncthreads();
    for (int i = t; i < N_TOK; i += 1024) {
        int l = label[i];
        int p = atomicAdd(&cur[l], 1);
        g_perm[base[l] + p] = i;
    }
}

// -------- grouped QKV GEMM: tf32 mma, 64x128 tile, warp 32x32 --------
// grid (64, 2, 27), block 256.
__global__ __launch_bounds__(256) void k_qkv(
    const float* __restrict__ x,
    const float* __restrict__ Wq, const float* __restrict__ bq,
    const float* __restrict__ Wk, const float* __restrict__ bk,
    const float* __restrict__ Wv, const float* __restrict__ bv)
{
    int g   = blockIdx.z % NEXP;
    int mat = blockIdx.z / NEXP;
    int goff = g_offsets[g];
    int gcnt = g_offsets[g + 1] - goff;
    int row0 = blockIdx.x * 64;
    if (row0 >= gcnt) return;
    int rows = min(64, gcnt - row0);
    int col0 = blockIdx.y * 128;

    const float* W; const float* bias; float* dst;
    if (mat == 0)      { W = Wq; bias = bq; dst = g_q; }
    else if (mat == 1) { W = Wk; bias = bk; dst = g_k; }
    else               { W = Wv; bias = bv; dst = g_v; }
    W    += (size_t)g * DMODEL * DMODEL;
    bias += g * DMODEL;

    __shared__ __align__(16) uint As[64 * AP];    // [m][k] tf32
    __shared__ __align__(16) uint Bs[16 * BP];    // [k][n] tf32
    __shared__ int Ts[64];

    int tid = threadIdx.x;
    if (tid < 64) Ts[tid] = g_perm[goff + row0 + min(tid, rows - 1)];
    __syncthreads();

    int lane = tid & 31, warp = tid >> 5;
    int wm = warp & 1, wn = warp >> 1;        // warps 2(m) x 4(n)
    int gq = lane >> 2, tg = lane & 3;

    float acc[2][4][4];
#pragma unroll
    for (int i = 0; i < 2; i++)
#pragma unroll
        for (int j = 0; j < 4; j++)
#pragma unroll
            for (int e = 0; e < 4; e++) acc[i][j][e] = 0.f;

    int am = tid & 63, aseg = tid >> 6;            // A loader: row am, k-seg aseg*4
    int bkk = tid >> 4, bn = (tid & 15) * 8;       // B loader: k-row bkk, cols bn..+8
    const float* Aptr = x + (size_t)Ts[am] * DMODEL + aseg * 4;
    const float* Bptr = W + (size_t)bkk * DMODEL + col0 + bn;

    float4 av  = *(const float4*)(Aptr);
    float4 bv0 = *(const float4*)(Bptr);
    float4 bv1 = *(const float4*)(Bptr + 4);

    for (int kk0 = 0; kk0 < DMODEL; kk0 += 16) {
        __syncthreads();
        {
            uint4 ua = {cvt_tf32(av.x), cvt_tf32(av.y), cvt_tf32(av.z), cvt_tf32(av.w)};
            *(uint4*)&As[am * AP + aseg * 4] = ua;
            uint4 ub0 = {cvt_tf32(bv0.x), cvt_tf32(bv0.y), cvt_tf32(bv0.z), cvt_tf32(bv0.w)};
            uint4 ub1 = {cvt_tf32(bv1.x), cvt_tf32(bv1.y), cvt_tf32(bv1.z), cvt_tf32(bv1.w)};
            *(uint4*)&Bs[bkk * BP + bn]     = ub0;
            *(uint4*)&Bs[bkk * BP + bn + 4] = ub1;
        }
        __syncthreads();
        if (kk0 + 16 < DMODEL) {
            av  = *(const float4*)(Aptr + kk0 + 16);
            bv0 = *(const float4*)(Bptr + (size_t)(kk0 + 16) * DMODEL);
            bv1 = *(const float4*)(Bptr + (size_t)(kk0 + 16) * DMODEL + 4);
        }
#pragma unroll
        for (int ka = 0; ka < 2; ka++) {
            int kb = ka * 8;
            uint af[2][4];
#pragma unroll
            for (int i = 0; i < 2; i++) {
                int r0 = wm * 32 + i * 16;
                af[i][0] = As[(r0 + gq)     * AP + kb + tg];
                af[i][1] = As[(r0 + gq + 8) * AP + kb + tg];
                af[i][2] = As[(r0 + gq)     * AP + kb + tg + 4];
                af[i][3] = As[(r0 + gq + 8) * AP + kb + tg + 4];
            }
#pragma unroll
            for (int j = 0; j < 4; j++) {
                int nc = wn * 32 + j * 8 + gq;
                uint b0 = Bs[(kb + tg)     * BP + nc];
                uint b1 = Bs[(kb + tg + 4) * BP + nc];
                mma_tf32(acc[0][j], af[0], b0, b1);
                mma_tf32(acc[1][j], af[1], b0, b1);
            }
        }
    }

#pragma unroll
    for (int i = 0; i < 2; i++) {
        int rbase = wm * 32 + i * 16 + gq;
#pragma unroll
        for (int j = 0; j < 4; j++) {
            int col = col0 + wn * 32 + j * 8 + tg * 2;
            float2 b2 = *(const float2*)&bias[col];
            if (rbase < rows) {
                float2 o = {acc[i][j][0] + b2.x, acc[i][j][1] + b2.y};
                *(float2*)&dst[(size_t)(goff + row0 + rbase) * DMODEL + col] = o;
            }
            if (rbase + 8 < rows) {
                float2 o = {acc[i][j][2] + b2.x, acc[i][j][3] + b2.y};
                *(float2*)&dst[(size_t)(goff + row0 + rbase + 8) * DMODEL + col] = o;
            }
        }
    }
}

// -------- per-group flash attention: no-max softmax, deferred l-reduce (unchanged) --------
// grid (64, 9, 4), block 256, dynamic smem 69632B.
__global__ __launch_bounds__(256) void k_attn()
{
    int g = blockIdx.y, h = blockIdx.z;
    int goff = g_offsets[g];
    int gcnt = g_offsets[g + 1] - goff;
    int row0 = blockIdx.x * 64;
    if (row0 >= gcnt) return;
    int rows = min(64, gcnt - row0);

    extern __shared__ __align__(16) float sm[];
    float* Qt = sm;                  // [d][qi] pitch 68 (pre-scaled by ATT_SCALE)
    float* Kt = Qt + 64 * 68;        // [d][kj] pitch 68
    float* Vs = Kt + 64 * 68;        // [kj][d] pitch 68
    float* Ps = Vs + 64 * 68;        // [qi][kj] pitch 68

    int tid = threadIdx.x;
    int r = tid >> 4, c = tid & 15;
    int li = tid & 63, seg = tid >> 6, d0 = seg * 16;  // loader mapping

    {
        const float* qptr = g_q + (size_t)(goff + row0 + min(li, rows - 1)) * DMODEL + h * DPH + d0;
#pragma unroll
        for (int f = 0; f < 4; f++) {
            float4 v = *(const float4*)(qptr + 4 * f);
            Qt[(d0 + 4 * f + 0) * 68 + li] = v.x * ATT_SCALE;
            Qt[(d0 + 4 * f + 1) * 68 + li] = v.y * ATT_SCALE;
            Qt[(d0 + 4 * f + 2) * 68 + li] = v.z * ATT_SCALE;
            Qt[(d0 + 4 * f + 3) * 68 + li] = v.w * ATT_SCALE;
        }
    }

    float lsum[4] = {0.f, 0.f, 0.f, 0.f};
    ull O2[4][2];
#pragma unroll
    for (int i = 0; i < 4; i++) { O2[i][0] = 0ull; O2[i][1] = 0ull; }

    float4 kr[4], vr[4];
    {
        int kcnt0 = min(64, gcnt);
        int krow = goff + min(li, kcnt0 - 1);
        const float* kptr = g_k + (size_t)krow * DMODEL + h * DPH + d0;
        const float* vptr = g_v + (size_t)krow * DMODEL + h * DPH + d0;
#pragma unroll
        for (int f = 0; f < 4; f++) {
            kr[f] = *(const float4*)(kptr + 4 * f);
            vr[f] = *(const float4*)(vptr + 4 * f);
        }
    }

    for (int kc0 = 0; kc0 < gcnt; kc0 += 64) {
        int kcnt = min(64, gcnt - kc0);
        __syncthreads();
#pragma unroll
        for (int f = 0; f < 4; f++) {
            Kt[(d0 + 4 * f + 0) * 68 + li] = kr[f].x;
            Kt[(d0 + 4 * f + 1) * 68 + li] = kr[f].y;
            Kt[(d0 + 4 * f + 2) * 68 + li] = kr[f].z;
            Kt[(d0 + 4 * f + 3) * 68 + li] = kr[f].w;
            *(float4*)&Vs[li * 68 + d0 + 4 * f] = vr[f];
        }
        __syncthreads();

        ull s2[4][2];
#pragma unroll
        for (int i = 0; i < 4; i++) { s2[i][0] = 0ull; s2[i][1] = 0ull; }
#pragma unroll 8
        for (int d = 0; d < 64; d++) {
            float4 a = *(const float4*)&Qt[d * 68 + 4 * r];
            ulonglong2 b = *(const ulonglong2*)&Kt[d * 68 + 4 * c];
            ull a0 = pack2(a.x), a1 = pack2(a.y), a2 = pack2(a.z), a3 = pack2(a.w);
            s2[0][0] = fma2(a0, b.x, s2[0][0]); s2[0][1] = fma2(a0, b.y, s2[0][1]);
            s2[1][0] = fma2(a1, b.x, s2[1][0]); s2[1][1] = fma2(a1, b.y, s2[1][1]);
            s2[2][0] = fma2(a2, b.x, s2[2][0]); s2[2][1] = fma2(a2, b.y, s2[2][1]);
            s2[3][0] = fma2(a3, b.x, s2[3][0]); s2[3][1] = fma2(a3, b.y, s2[3][1]);
        }

        bool va0 = (4 * c + 0) < kcnt, va1 = (4 * c + 1) < kcnt;
        bool va2 = (4 * c + 2) < kcnt, va3 = (4 * c + 3) < kcnt;
#pragma unroll
        for (int i = 0; i < 4; i++) {
            float2 sa = unpack2(s2[i][0]);
            float2 sb = unpack2(s2[i][1]);
            float p0 = va0 ? __expf(sa.x) : 0.f;
            float p1 = va1 ? __expf(sa.y) : 0.f;
            float p2 = va2 ? __expf(sb.x) : 0.f;
            float p3 = va3 ? __expf(sb.y) : 0.f;
            lsum[i] += (p0 + p1) + (p2 + p3);
            float4 pv = {p0, p1, p2, p3};
            *(float4*)&Ps[(4 * r + i) * 68 + 4 * c] = pv;
        }

        if (kc0 + 64 < gcnt) {
            int kcn = min(64, gcnt - kc0 - 64);
            int krow = goff + kc0 + 64 + min(li, kcn - 1);
            const float* kptr = g_k + (size_t)krow * DMODEL + h * DPH + d0;
            const float* vptr = g_v + (size_t)krow * DMODEL + h * DPH + d0;
#pragma unroll
            for (int f = 0; f < 4; f++) {
                kr[f] = *(const float4*)(kptr + 4 * f);
                vr[f] = *(const float4*)(vptr + 4 * f);
            }
        }
        __syncthreads();

#pragma unroll 4
        for (int kj = 0; kj < 64; kj += 4) {
            float4 pp0 = *(const float4*)&Ps[(4 * r + 0) * 68 + kj];
            float4 pp1 = *(const float4*)&Ps[(4 * r + 1) * 68 + kj];
            float4 pp2 = *(const float4*)&Ps[(4 * r + 2) * 68 + kj];
            float4 pp3 = *(const float4*)&Ps[(4 * r + 3) * 68 + kj];
#pragma unroll
            for (int j = 0; j < 4; j++) {
                ulonglong2 vv = *(const ulonglong2*)&Vs[(kj + j) * 68 + 4 * c];
                float p0 = (j == 0) ? pp0.x : (j == 1) ? pp0.y : (j == 2) ? pp0.z : pp0.w;
                float p1 = (j == 0) ? pp1.x : (j == 1) ? pp1.y : (j == 2) ? pp1.z : pp1.w;
                float p2 = (j == 0) ? pp2.x : (j == 1) ? pp2.y : (j == 2) ? pp2.z : pp2.w;
                float p3 = (j == 0) ? pp3.x : (j == 1) ? pp3.y : (j == 2) ? pp3.z : pp3.w;
                ull q0 = pack2(p0), q1 = pack2(p1), q2 = pack2(p2), q3 = pack2(p3);
                O2[0][0] = fma2(q0, vv.x, O2[0][0]); O2[0][1] = fma2(q0, vv.y, O2[0][1]);
                O2[1][0] = fma2(q1, vv.x, O2[1][0]); O2[1][1] = fma2(q1, vv.y, O2[1][1]);
                O2[2][0] = fma2(q2, vv.x, O2[2][0]); O2[2][1] = fma2(q2, vv.y, O2[2][1]);
                O2[3][0] = fma2(q3, vv.x, O2[3][0]); O2[3][1] = fma2(q3, vv.y, O2[3][1]);
            }
        }
    }

#pragma unroll
    for (int i = 0; i < 4; i++) {
        float ps = lsum[i];
        ps += __shfl_xor_sync(0xffffffffu, ps, 1);
        ps += __shfl_xor_sync(0xffffffffu, ps, 2);
        ps += __shfl_xor_sync(0xffffffffu, ps, 4);
        ps += __shfl_xor_sync(0xffffffffu, ps, 8);
        lsum[i] = ps;
    }

#pragma unroll
    for (int i = 0; i < 4; i++) {
        int qrow = 4 * r + i;
        if (qrow < rows) {
            float inv = 1.f / lsum[i];
            float2 oa = unpack2(O2[i][0]);
            float2 ob = unpack2(O2[i][1]);
            float4 o = {oa.x * inv, oa.y * inv, ob.x * inv, ob.y * inv};
            *(float4*)&g_ctx[(size_t)(goff + row0 + qrow) * DMODEL + h * DPH + 4 * c] = o;
        }
    }
}

// -------- output projection + residual: tf32 mma, 64x128 tile --------
// grid (64, 2), block 256. g_h[sorted] = x[perm] + ctx[sorted] @ Wf + bf
__global__ __launch_bounds__(256) void k_proj(
    const float* __restrict__ x,
    const float* __restrict__ Wf, const float* __restrict__ bf)
{
    int row0 = blockIdx.x * 64;
    int col0 = blockIdx.y * 128;

    __shared__ __align__(16) uint As[64 * AP];
    __shared__ __align__(16) uint Bs[16 * BP];
    __shared__ int Ts[64];

    int tid = threadIdx.x;
    if (tid < 64) Ts[tid] = g_perm[row0 + tid];

    int lane = tid & 31, warp = tid >> 5;
    int wm = warp & 1, wn = warp >> 1;
    int gq = lane >> 2, tg = lane & 3;

    float acc[2][4][4];
#pragma unroll
    for (int i = 0; i < 2; i++)
#pragma unroll
        for (int j = 0; j < 4; j++)
#pragma unroll
            for (int e = 0; e < 4; e++) acc[i][j][e] = 0.f;

    int am = tid & 63, aseg = tid >> 6;
    int bkk = tid >> 4, bn = (tid & 15) * 8;
    const float* Aptr = g_ctx + (size_t)(row0 + am) * DMODEL + aseg * 4;
    const float* Bptr = Wf + (size_t)bkk * DMODEL + col0 + bn;

    float4 av  = *(const float4*)(Aptr);
    float4 bv0 = *(const float4*)(Bptr);
    float4 bv1 = *(const float4*)(Bptr + 4);

    for (int kk0 = 0; kk0 < DMODEL; kk0 += 16) {
        __syncthreads();
        {
            uint4 ua = {cvt_tf32(av.x), cvt_tf32(av.y), cvt_tf32(av.z), cvt_tf32(av.w)};
            *(uint4*)&As[am * AP + aseg * 4] = ua;
            uint4 ub0 = {cvt_tf32(bv0.x), cvt_tf32(bv0.y), cvt_tf32(bv0.z), cvt_tf32(bv0.w)};
            uint4 ub1 = {cvt_tf32(bv1.x), cvt_tf32(bv1.y), cvt_tf32(bv1.z), cvt_tf32(bv1.w)};
            *(uint4*)&Bs[bkk * BP + bn]     = ub0;
            *(uint4*)&Bs[bkk * BP + bn + 4] = ub1;
        }
        __syncthreads();
        if (kk0 + 16 < DMODEL) {
            av  = *(const float4*)(Aptr + kk0 + 16);
            bv0 = *(const float4*)(Bptr + (size_t)(kk0 + 16) * DMODEL);
            bv1 = *(const float4*)(Bptr + (size_t)(kk0 + 16) * DMODEL + 4);
        }
#pragma unroll
        for (int ka = 0; ka < 2; ka++) {
            int kb = ka * 8;
            uint af[2][4];
#pragma unroll
            for (int i = 0; i < 2; i++) {
                int r0 = wm * 32 + i * 16;
                af[i][0] = As[(r0 + gq)     * AP + kb + tg];
                af[i][1] = As[(r0 + gq + 8) * AP + kb + tg];
                af[i][2] = As[(r0 + gq)     * AP + kb + tg + 4];
                af[i][3] = As[(r0 + gq + 8) * AP + kb + tg + 4];
            }
#pragma unroll
            for (int j = 0; j < 4; j++) {
                int nc = wn * 32 + j * 8 + gq;
                uint b0 = Bs[(kb + tg)     * BP + nc];
                uint b1 = Bs[(kb + tg + 4) * BP + nc];
                mma_tf32(acc[0][j], af[0], b0, b1);
                mma_tf32(acc[1][j], af[1], b0, b1);
            }
        }
    }

#pragma unroll
    for (int i = 0; i < 2; i++) {
        int rbase = wm * 32 + i * 16 + gq;
#pragma unroll
        for (int j = 0; j < 4; j++) {
            int col = col0 + wn * 32 + j * 8 + tg * 2;
            float2 b2 = *(const float2*)&bf[col];
            {
                int m = rbase;
                float2 xv = *(const float2*)&x[(size_t)Ts[m] * DMODEL + col];
                float2 o = {acc[i][j][0] + b2.x + xv.x, acc[i][j][1] + b2.y + xv.y};
                *(float2*)&g_h[(size_t)(row0 + m) * DMODEL + col] = o;
            }
            {
                int m = rbase + 8;
                float2 xv = *(const float2*)&x[(size_t)Ts[m] * DMODEL + col];
                float2 o = {acc[i][j][2] + b2.x + xv.x, acc[i][j][3] + b2.y + xv.y};
                *(float2*)&g_h[(size_t)(row0 + m) * DMODEL + col] = o;
            }
        }
    }
}

// -------- LayerNorm (sorted row -> scatter to original) --------
__global__ void k_ln(const float* __restrict__ gamma, const float* __restrict__ beta,
                     float* __restrict__ out)
{
    int srow = blockIdx.x;
    int tid = threadIdx.x;
    float v = g_h[(size_t)srow * DMODEL + tid];
    float s = v, sq = v * v;
#pragma unroll
    for (int off = 16; off > 0; off >>= 1) {
        s  += __shfl_xor_sync(0xffffffffu, s, off);
        sq += __shfl_xor_sync(0xffffffffu, sq, off);
    }
    __shared__ float rs[8], rq[8];
    int w = tid >> 5;
    if ((tid & 31) == 0) { rs[w] = s; rq[w] = sq; }
    __syncthreads();
    s = 0.f; sq = 0.f;
#pragma unroll
    for (int i = 0; i < 8; i++) { s += rs[i]; sq += rq[i]; }
    float mean = s * (1.f / DMODEL);
    float var  = sq * (1.f / DMODEL) - mean * mean;
    float inv  = rsqrtf(var + LN_EPS);
    int orow = g_perm[srow];
    out[(size_t)orow * DMODEL + tid] = gamma[tid] * (v - mean) * inv + beta[tid];
}

// -------- launch --------
extern "C" void kernel_launch(void* const* d_in, const int* in_sizes, int n_in,
                              void* d_out, int out_size)
{
    const float* x     = (const float*)d_in[0];
    const int*   label = (const int*)  d_in[1];
    const float* Wq    = (const float*)d_in[2];
    const float* bq    = (const float*)d_in[3];
    const float* Wk    = (const float*)d_in[4];
    const float* bk    = (const float*)d_in[5];
    const float* Wv    = (const float*)d_in[6];
    const float* bv    = (const float*)d_in[7];
    const float* Wf    = (const float*)d_in[8];
    const float* bf    = (const float*)d_in[9];
    const float* gamma = (const float*)d_in[10];
    const float* beta  = (const float*)d_in[11];
    float* out = (float*)d_out;

    static bool attr_done = false;
    if (!attr_done) {
        cudaFuncSetAttribute(k_attn, cudaFuncAttributeMaxDynamicSharedMemorySize, 4 * 64 * 68 * 4);
        cudaFuncSetAttribute(k_attn, cudaFuncAttributePreferredSharedMemoryCarveout, 100);
        attr_done = true;
    }

    k_sort<<<1, 1024>>>(label);
    k_qkv<<<dim3(64, 2, 3 * NEXP), 256>>>(x, Wq, bq, Wk, bk, Wv, bv);
    k_attn<<<dim3(64, NEXP, NHEAD), 256, 4 * 64 * 68 * 4>>>();
    k_proj<<<dim3(64, 2), 256>>>(x, Wf, bf);
    k_ln<<<N_TOK, 256>>>(gamma, beta, out);
}

// round 8
// speedup vs baseline: 1.5234x; 1.3143x over previous
#include <cuda_runtime.h>
#include <math.h>

#define N_TOK   4096
#define DMODEL  256
#define NHEAD   4
#define DPH     64
#define NEXP    9
#define LN_EPS  1e-5f
#define ATT_SCALE 0.25f   // (dph // num_heads) ** -0.5 = 16^-0.5

typedef unsigned long long ull;
typedef unsigned int uint;

// -------- device scratch (sorted-domain layout) --------
__device__ float g_q[N_TOK * DMODEL];
__device__ float g_k[N_TOK * DMODEL];
__device__ float g_v[N_TOK * DMODEL];
__device__ float g_ctx[N_TOK * DMODEL];
__device__ float g_h[N_TOK * DMODEL];
__device__ int   g_perm[N_TOK];       // sorted pos -> original token
__device__ int   g_offsets[NEXP + 1];

// -------- tf32 mma helpers --------
__device__ __forceinline__ uint cvt_tf32(float x) {
    uint u; asm("cvt.rna.tf32.f32 %0, %1;" : "=r"(u) : "f"(x)); return u;
}
__device__ __forceinline__ void mma_tf32(float* d, const uint* a, uint b0, uint b1) {
    asm("mma.sync.aligned.m16n8k8.row.col.f32.tf32.tf32.f32 "
        "{%0,%1,%2,%3}, {%4,%5,%6,%7}, {%8,%9}, {%0,%1,%2,%3};"
        : "+f"(d[0]), "+f"(d[1]), "+f"(d[2]), "+f"(d[3])
        : "r"(a[0]), "r"(a[1]), "r"(a[2]), "r"(a[3]), "r"(b0), "r"(b1));
}

#define AP 20    // qkv/proj As pitch (uints)
#define BP 132   // qkv/proj Bs pitch (uints)
#define TP 68    // attn tile pitch (uints/floats)

// -------- fused counting sort (1 block) --------
__global__ void k_sort(const int* __restrict__ label) {
    __shared__ int hist[NEXP], base[NEXP + 1], cur[NEXP];
    int t = threadIdx.x;
    if (t < NEXP) { hist[t] = 0; cur[t] = 0; }
    __syncthreads();
    for (int i = t; i < N_TOK; i += 1024) atomicAdd(&hist[label[i]], 1);
    __syncthreads();
    if (t == 0) {
        int off = 0;
        for (int e = 0; e < NEXP; e++) { base[e] = off; g_offsets[e] = off; off += hist[e]; }
        base[NEXP] = off; g_offsets[NEXP] = off;
    }
    __syncthreads();
    for (int i = t; i < N_TOK; i += 1024) {
        int l = label[i];
        int p = atomicAdd(&cur[l], 1);
        g_perm[base[l] + p] = i;
    }
}

// -------- grouped QKV GEMM: tf32 mma, 64x128 tile, warp 32x32 (unchanged R7) --------
__global__ __launch_bounds__(256) void k_qkv(
    const float* __restrict__ x,
    const float* __restrict__ Wq, const float* __restrict__ bq,
    const float* __restrict__ Wk, const float* __restrict__ bk,
    const float* __restrict__ Wv, const float* __restrict__ bv)
{
    int g   = blockIdx.z % NEXP;
    int mat = blockIdx.z / NEXP;
    int goff = g_offsets[g];
    int gcnt = g_offsets[g + 1] - goff;
    int row0 = blockIdx.x * 64;
    if (row0 >= gcnt) return;
    int rows = min(64, gcnt - row0);
    int col0 = blockIdx.y * 128;

    const float* W; const float* bias; float* dst;
    if (mat == 0)      { W = Wq; bias = bq; dst = g_q; }
    else if (mat == 1) { W = Wk; bias = bk; dst = g_k; }
    else               { W = Wv; bias = bv; dst = g_v; }
    W    += (size_t)g * DMODEL * DMODEL;
    bias += g * DMODEL;

    __shared__ __align__(16) uint As[64 * AP];
    __shared__ __align__(16) uint Bs[16 * BP];
    __shared__ int Ts[64];

    int tid = threadIdx.x;
    if (tid < 64) Ts[tid] = g_perm[goff + row0 + min(tid, rows - 1)];
    __syncthreads();

    int lane = tid & 31, warp = tid >> 5;
    int wm = warp & 1, wn = warp >> 1;
    int gq = lane >> 2, tg = lane & 3;

    float acc[2][4][4];
#pragma unroll
    for (int i = 0; i < 2; i++)
#pragma unroll
        for (int j = 0; j < 4; j++)
#pragma unroll
            for (int e = 0; e < 4; e++) acc[i][j][e] = 0.f;

    int am = tid & 63, aseg = tid >> 6;
    int bkk = tid >> 4, bn = (tid & 15) * 8;
    const float* Aptr = x + (size_t)Ts[am] * DMODEL + aseg * 4;
    const float* Bptr = W + (size_t)bkk * DMODEL + col0 + bn;

    float4 av  = *(const float4*)(Aptr);
    float4 bv0 = *(const float4*)(Bptr);
    float4 bv1 = *(const float4*)(Bptr + 4);

    for (int kk0 = 0; kk0 < DMODEL; kk0 += 16) {
        __syncthreads();
        {
            uint4 ua = {cvt_tf32(av.x), cvt_tf32(av.y), cvt_tf32(av.z), cvt_tf32(av.w)};
            *(uint4*)&As[am * AP + aseg * 4] = ua;
            uint4 ub0 = {cvt_tf32(bv0.x), cvt_tf32(bv0.y), cvt_tf32(bv0.z), cvt_tf32(bv0.w)};
            uint4 ub1 = {cvt_tf32(bv1.x), cvt_tf32(bv1.y), cvt_tf32(bv1.z), cvt_tf32(bv1.w)};
            *(uint4*)&Bs[bkk * BP + bn]     = ub0;
            *(uint4*)&Bs[bkk * BP + bn + 4] = ub1;
        }
        __syncthreads();
        if (kk0 + 16 < DMODEL) {
            av  = *(const float4*)(Aptr + kk0 + 16);
            bv0 = *(const float4*)(Bptr + (size_t)(kk0 + 16) * DMODEL);
            bv1 = *(const float4*)(Bptr + (size_t)(kk0 + 16) * DMODEL + 4);
        }
#pragma unroll
        for (int ka = 0; ka < 2; ka++) {
            int kb = ka * 8;
            uint af[2][4];
#pragma unroll
            for (int i = 0; i < 2; i++) {
                int r0 = wm * 32 + i * 16;
                af[i][0] = As[(r0 + gq)     * AP + kb + tg];
                af[i][1] = As[(r0 + gq + 8) * AP + kb + tg];
                af[i][2] = As[(r0 + gq)     * AP + kb + tg + 4];
                af[i][3] = As[(r0 + gq + 8) * AP + kb + tg + 4];
            }
#pragma unroll
            for (int j = 0; j < 4; j++) {
                int nc = wn * 32 + j * 8 + gq;
                uint b0 = Bs[(kb + tg)     * BP + nc];
                uint b1 = Bs[(kb + tg + 4) * BP + nc];
                mma_tf32(acc[0][j], af[0], b0, b1);
                mma_tf32(acc[1][j], af[1], b0, b1);
            }
        }
    }

#pragma unroll
    for (int i = 0; i < 2; i++) {
        int rbase = wm * 32 + i * 16 + gq;
#pragma unroll
        for (int j = 0; j < 4; j++) {
            int col = col0 + wn * 32 + j * 8 + tg * 2;
            float2 b2 = *(const float2*)&bias[col];
            if (rbase < rows) {
                float2 o = {acc[i][j][0] + b2.x, acc[i][j][1] + b2.y};
                *(float2*)&dst[(size_t)(goff + row0 + rbase) * DMODEL + col] = o;
            }
            if (rbase + 8 < rows) {
                float2 o = {acc[i][j][2] + b2.x, acc[i][j][3] + b2.y};
                *(float2*)&dst[(size_t)(goff + row0 + rbase + 8) * DMODEL + col] = o;
            }
        }
    }
}

// -------- per-group flash attention: tf32 mma for QK^T and P·V --------
// grid (64, 9, 4), block 256 (8 warps, 2m x 4n), dynamic smem 4*64*TP*4 = 69632B.
__global__ __launch_bounds__(256) void k_attn()
{
    int g = blockIdx.y, h = blockIdx.z;
    int goff = g_offsets[g];
    int gcnt = g_offsets[g + 1] - goff;
    int row0 = blockIdx.x * 64;
    if (row0 >= gcnt) return;
    int rows = min(64, gcnt - row0);

    extern __shared__ __align__(16) uint smu[];
    uint* Qs = smu;                  // [qi][d]  pitch TP, tf32 (pre-scaled)
    uint* Ks = Qs + 64 * TP;         // [kj][d]  pitch TP, tf32
    uint* Vt = Ks + 64 * TP;         // [d][kj]  pitch TP, tf32 (transposed)
    uint* Ps = Vt + 64 * TP;         // [qi][kj] pitch TP, tf32

    int tid = threadIdx.x;
    int lane = tid & 31, warp = tid >> 5;
    int wm = warp & 1, wn = warp >> 1;           // 2(m) x 4(n)
    int gq = lane >> 2, tg = lane & 3;
    int li = tid & 63, seg = tid >> 6, d0 = seg * 16;   // loader mapping

    // stage Q (once): [qi][d], scaled, tf32
    {
        const float* qptr = g_q + (size_t)(goff + row0 + min(li, rows - 1)) * DMODEL + h * DPH + d0;
#pragma unroll
        for (int f = 0; f < 4; f++) {
            float4 v = *(const float4*)(qptr + 4 * f);
            uint4 u = {cvt_tf32(v.x * ATT_SCALE), cvt_tf32(v.y * ATT_SCALE),
                       cvt_tf32(v.z * ATT_SCALE), cvt_tf32(v.w * ATT_SCALE)};
            *(uint4*)&Qs[li * TP + d0 + 4 * f] = u;
        }
    }

    float O[2][2][4];                 // [mfrag][nfrag][elt] over (64q x 64d)
#pragma unroll
    for (int i = 0; i < 2; i++)
#pragma unroll
        for (int j = 0; j < 2; j++)
#pragma unroll
            for (int e = 0; e < 4; e++) O[i][j][e] = 0.f;
    float lsum[4] = {0.f, 0.f, 0.f, 0.f};   // rows wm*32 + {gq, gq+8, gq+16, gq+24}

    // prefetch tile 0 K/V
    float4 kr[4], vr[4];
    {
        int krow = goff + min(li, min(64, gcnt) - 1);
        const float* kptr = g_k + (size_t)krow * DMODEL + h * DPH + d0;
        const float* vptr = g_v + (size_t)krow * DMODEL + h * DPH + d0;
#pragma unroll
        for (int f = 0; f < 4; f++) {
            kr[f] = *(const float4*)(kptr + 4 * f);
            vr[f] = *(const float4*)(vptr + 4 * f);
        }
    }

    for (int kc0 = 0; kc0 < gcnt; kc0 += 64) {
        int kcnt = min(64, gcnt - kc0);
        __syncthreads();   // prior PV reads (Ps/Vt) done; Qs stores ordered on iter 0
        // stage K [kj][d] (vector) + V transposed [d][kj] (scalar)
#pragma unroll
        for (int f = 0; f < 4; f++) {
            uint4 uk = {cvt_tf32(kr[f].x), cvt_tf32(kr[f].y), cvt_tf32(kr[f].z), cvt_tf32(kr[f].w)};
            *(uint4*)&Ks[li * TP + d0 + 4 * f] = uk;
            Vt[(d0 + 4 * f + 0) * TP + li] = cvt_tf32(vr[f].x);
            Vt[(d0 + 4 * f + 1) * TP + li] = cvt_tf32(vr[f].y);
            Vt[(d0 + 4 * f + 2) * TP + li] = cvt_tf32(vr[f].z);
            Vt[(d0 + 4 * f + 3) * TP + li] = cvt_tf32(vr[f].w);
        }
        __syncthreads();

        // ---- S = Q K^T via mma (warp tile 32x16) ----
        float S[2][2][4];
#pragma unroll
        for (int i = 0; i < 2; i++)
#pragma unroll
            for (int j = 0; j < 2; j++)
#pragma unroll
                for (int e = 0; e < 4; e++) S[i][j][e] = 0.f;
#pragma unroll
        for (int kb = 0; kb < 64; kb += 8) {
            uint af[2][4];
#pragma unroll
            for (int i = 0; i < 2; i++) {
                int r0 = wm * 32 + i * 16;
                af[i][0] = Qs[(r0 + gq)     * TP + kb + tg];
                af[i][1] = Qs[(r0 + gq + 8) * TP + kb + tg];
                af[i][2] = Qs[(r0 + gq)     * TP + kb + tg + 4];
                af[i][3] = Qs[(r0 + gq + 8) * TP + kb + tg + 4];
            }
#pragma unroll
            for (int j = 0; j < 2; j++) {
                int nc = wn * 16 + j * 8 + gq;
                uint b0 = Ks[nc * TP + kb + tg];
                uint b1 = Ks[nc * TP + kb + tg + 4];
                mma_tf32(S[0][j], af[0], b0, b1);
                mma_tf32(S[1][j], af[1], b0, b1);
            }
        }

        // ---- exp (no-max; scores bounded) + mask + P->smem + partial lsum ----
#pragma unroll
        for (int i = 0; i < 2; i++) {
            int r_a = wm * 32 + i * 16 + gq;
#pragma unroll
            for (int j = 0; j < 2; j++) {
                int c0 = wn * 16 + j * 8 + tg * 2;
                bool v0 = c0 < kcnt, v1 = c0 + 1 < kcnt;
                float p00 = v0 ? __expf(S[i][j][0]) : 0.f;
                float p01 = v1 ? __expf(S[i][j][1]) : 0.f;
                float p10 = v0 ? __expf(S[i][j][2]) : 0.f;
                float p11 = v1 ? __expf(S[i][j][3]) : 0.f;
                lsum[i * 2 + 0] += p00 + p01;
                lsum[i * 2 + 1] += p10 + p11;
                uint2 ua = {cvt_tf32(p00), cvt_tf32(p01)};
                *(uint2*)&Ps[r_a * TP + c0] = ua;
                uint2 ub = {cvt_tf32(p10), cvt_tf32(p11)};
                *(uint2*)&Ps[(r_a + 8) * TP + c0] = ub;
            }
        }

        // prefetch next tile K/V
        if (kc0 + 64 < gcnt) {
            int krow = goff + kc0 + 64 + min(li, min(64, gcnt - kc0 - 64) - 1);
            const float* kptr = g_k + (size_t)krow * DMODEL + h * DPH + d0;
            const float* vptr = g_v + (size_t)krow * DMODEL + h * DPH + d0;
#pragma unroll
            for (int f = 0; f < 4; f++) {
                kr[f] = *(const float4*)(kptr + 4 * f);
                vr[f] = *(const float4*)(vptr + 4 * f);
            }
        }
        __syncthreads();   // Ps visible to all warps

        // ---- O += P V via mma (warp tile 32q x 16d) ----
#pragma unroll
        for (int kb = 0; kb < 64; kb += 8) {
            uint af[2][4];
#pragma unroll
            for (int i = 0; i < 2; i++) {
                int r0 = wm * 32 + i * 16;
                af[i][0] = Ps[(r0 + gq)     * TP + kb + tg];
                af[i][1] = Ps[(r0 + gq + 8) * TP + kb + tg];
                af[i][2] = Ps[(r0 + gq)     * TP + kb + tg + 4];
                af[i][3] = Ps[(r0 + gq + 8) * TP + kb + tg + 4];
            }
#pragma unroll
            for (int j = 0; j < 2; j++) {
                int nc = wn * 16 + j * 8 + gq;   // d column
                uint b0 = Vt[nc * TP + kb + tg];
                uint b1 = Vt[nc * TP + kb + tg + 4];
                mma_tf32(O[0][j], af[0], b0, b1);
                mma_tf32(O[1][j], af[1], b0, b1);
            }
        }
    }

    // ---- final row-sum reduction: intra-quad shfl, then across the 4 n-warps via smem ----
#pragma unroll
    for (int i = 0; i < 4; i++) {
        float ps = lsum[i];
        ps += __shfl_xor_sync(0xffffffffu, ps, 1);
        ps += __shfl_xor_sync(0xffffffffu, ps, 2);
        lsum[i] = ps;
    }
    float* red = (float*)Ps;          // reuse Ps as [row][wn] float buffer (64*4)
    __syncthreads();                  // PV reads of Ps done
    if (tg == 0) {
#pragma unroll
        for (int idx = 0; idx < 4; idx++) {
            int row = wm * 32 + (idx >> 1) * 16 + (idx & 1) * 8 + gq;
            red[row * 4 + wn] = lsum[idx];
        }
    }
    __syncthreads();

#pragma unroll
    for (int i = 0; i < 2; i++) {
#pragma unroll
        for (int b = 0; b < 2; b++) {
            int row = wm * 32 + i * 16 + b * 8 + gq;
            if (row < rows) {
                float tot = red[row * 4 + 0] + red[row * 4 + 1] + red[row * 4 + 2] + red[row * 4 + 3];
                float inv = 1.f / tot;
#pragma unroll
                for (int j = 0; j < 2; j++) {
                    int col = wn * 16 + j * 8 + tg * 2;
                    float2 o = {O[i][j][b * 2 + 0] * inv, O[i][j][b * 2 + 1] * inv};
                    *(float2*)&g_ctx[(size_t)(goff + row0 + row) * DMODEL + h * DPH + col] = o;
                }
            }
        }
    }
}

// -------- output projection + residual: tf32 mma, 64x128 tile (unchanged R7) --------
__global__ __launch_bounds__(256) void k_proj(
    const float* __restrict__ x,
    const float* __restrict__ Wf, const float* __restrict__ bf)
{
    int row0 = blockIdx.x * 64;
    int col0 = blockIdx.y * 128;

    __shared__ __align__(16) uint As[64 * AP];
    __shared__ __align__(16) uint Bs[16 * BP];
    __shared__ int Ts[64];

    int tid = threadIdx.x;
    if (tid < 64) Ts[tid] = g_perm[row0 + tid];

    int lane = tid & 31, warp = tid >> 5;
    int wm = warp & 1, wn = warp >> 1;
    int gq = lane >> 2, tg = lane & 3;

    float acc[2][4][4];
#pragma unroll
    for (int i = 0; i < 2; i++)
#pragma unroll
        for (int j = 0; j < 4; j++)
#pragma unroll
            for (int e = 0; e < 4; e++) acc[i][j][e] = 0.f;

    int am = tid & 63, aseg = tid >> 6;
    int bkk = tid >> 4, bn = (tid & 15) * 8;
    const float* Aptr = g_ctx + (size_t)(row0 + am) * DMODEL + aseg * 4;
    const float* Bptr = Wf + (size_t)bkk * DMODEL + col0 + bn;

    float4 av  = *(const float4*)(Aptr);
    float4 bv0 = *(const float4*)(Bptr);
    float4 bv1 = *(const float4*)(Bptr + 4);

    for (int kk0 = 0; kk0 < DMODEL; kk0 += 16) {
        __syncthreads();
        {
            uint4 ua = {cvt_tf32(av.x), cvt_tf32(av.y), cvt_tf32(av.z), cvt_tf32(av.w)};
            *(uint4*)&As[am * AP + aseg * 4] = ua;
            uint4 ub0 = {cvt_tf32(bv0.x), cvt_tf32(bv0.y), cvt_tf32(bv0.z), cvt_tf32(bv0.w)};
            uint4 ub1 = {cvt_tf32(bv1.x), cvt_tf32(bv1.y), cvt_tf32(bv1.z), cvt_tf32(bv1.w)};
            *(uint4*)&Bs[bkk * BP + bn]     = ub0;
            *(uint4*)&Bs[bkk * BP + bn + 4] = ub1;
        }
        __syncthreads();
        if (kk0 + 16 < DMODEL) {
            av  = *(const float4*)(Aptr + kk0 + 16);
            bv0 = *(const float4*)(Bptr + (size_t)(kk0 + 16) * DMODEL);
            bv1 = *(const float4*)(Bptr + (size_t)(kk0 + 16) * DMODEL + 4);
        }
#pragma unroll
        for (int ka = 0; ka < 2; ka++) {
            int kb = ka * 8;
            uint af[2][4];
#pragma unroll
            for (int i = 0; i < 2; i++) {
                int r0 = wm * 32 + i * 16;
                af[i][0] = As[(r0 + gq)     * AP + kb + tg];
                af[i][1] = As[(r0 + gq + 8) * AP + kb + tg];
                af[i][2] = As[(r0 + gq)     * AP + kb + tg + 4];
                af[i][3] = As[(r0 + gq + 8) * AP + kb + tg + 4];
            }
#pragma unroll
            for (int j = 0; j < 4; j++) {
                int nc = wn * 32 + j * 8 + gq;
                uint b0 = Bs[(kb + tg)     * BP + nc];
                uint b1 = Bs[(kb + tg + 4) * BP + nc];
                mma_tf32(acc[0][j], af[0], b0, b1);
                mma_tf32(acc[1][j], af[1], b0, b1);
            }
        }
    }

#pragma unroll
    for (int i = 0; i < 2; i++) {
        int rbase = wm * 32 + i * 16 + gq;
#pragma unroll
        for (int j = 0; j < 4; j++) {
            int col = col0 + wn * 32 + j * 8 + tg * 2;
            float2 b2 = *(const float2*)&bf[col];
            {
                int m = rbase;
                float2 xv = *(const float2*)&x[(size_t)Ts[m] * DMODEL + col];
                float2 o = {acc[i][j][0] + b2.x + xv.x, acc[i][j][1] + b2.y + xv.y};
                *(float2*)&g_h[(size_t)(row0 + m) * DMODEL + col] = o;
            }
            {
                int m = rbase + 8;
                float2 xv = *(const float2*)&x[(size_t)Ts[m] * DMODEL + col];
                float2 o = {acc[i][j][2] + b2.x + xv.x, acc[i][j][3] + b2.y + xv.y};
                *(float2*)&g_h[(size_t)(row0 + m) * DMODEL + col] = o;
            }
        }
    }
}

// -------- LayerNorm (sorted row -> scatter to original) --------
__global__ void k_ln(const float* __restrict__ gamma, const float* __restrict__ beta,
                     float* __restrict__ out)
{
    int srow = blockIdx.x;
    int tid = threadIdx.x;
    float v = g_h[(size_t)srow * DMODEL + tid];
    float s = v, sq = v * v;
#pragma unroll
    for (int off = 16; off > 0; off >>= 1) {
        s  += __shfl_xor_sync(0xffffffffu, s, off);
        sq += __shfl_xor_sync(0xffffffffu, sq, off);
    }
    __shared__ float rs[8], rq[8];
    int w = tid >> 5;
    if ((tid & 31) == 0) { rs[w] = s; rq[w] = sq; }
    __syncthreads();
    s = 0.f; sq = 0.f;
#pragma unroll
    for (int i = 0; i < 8; i++) { s += rs[i]; sq += rq[i]; }
    float mean = s * (1.f / DMODEL);
    float var  = sq * (1.f / DMODEL) - mean * mean;
    float inv  = rsqrtf(var + LN_EPS);
    int orow = g_perm[srow];
    out[(size_t)orow * DMODEL + tid] = gamma[tid] * (v - mean) * inv + beta[tid];
}

// -------- launch --------
extern "C" void kernel_launch(void* const* d_in, const int* in_sizes, int n_in,
                              void* d_out, int out_size)
{
    const float* x     = (const float*)d_in[0];
    const int*   label = (const int*)  d_in[1];
    const float* Wq    = (const float*)d_in[2];
    const float* bq    = (const float*)d_in[3];
    const float* Wk    = (const float*)d_in[4];
    const float* bk    = (const float*)d_in[5];
    const float* Wv    = (const float*)d_in[6];
    const float* bv    = (const float*)d_in[7];
    const float* Wf    = (const float*)d_in[8];
    const float* bf    = (const float*)d_in[9];
    const float* gamma = (const float*)d_in[10];
    const float* beta  = (const float*)d_in[11];
    float* out = (float*)d_out;

    static bool attr_done = false;
    if (!attr_done) {
        cudaFuncSetAttribute(k_attn, cudaFuncAttributeMaxDynamicSharedMemorySize, 4 * 64 * TP * 4);
        cudaFuncSetAttribute(k_attn, cudaFuncAttributePreferredSharedMemoryCarveout, 100);
        attr_done = true;
    }

    k_sort<<<1, 1024>>>(label);
    k_qkv<<<dim3(64, 2, 3 * NEXP), 256>>>(x, Wq, bq, Wk, bk, Wv, bv);
    k_attn<<<dim3(64, NEXP, NHEAD), 256, 4 * 64 * TP * 4>>>();
    k_proj<<<dim3(64, 2), 256>>>(x, Wf, bf);
    k_ln<<<N_TOK, 256>>>(gamma, beta, out);
}